// round 15
// baseline (speedup 1.0000x reference)
#include <cuda_runtime.h>
#include <cuda_fp16.h>
#include <cstdint>
#include <math.h>

#define T 2048      // tokens
#define D 1024      // model dim
#define H 2816      // ffn hidden
#define E 8         // experts
#define NPAIR (T*2) // token-expert pairs

#define BM 128
#define BN 64
#define BK 32
#define STRIDE 80   // padded bytes per k-row (multiple of 16; conflict-free)

// ---------------- device globals (no allocation allowed) ----------------
__device__ int   g_pidx[NPAIR];
__device__ float g_pw[NPAIR];
__device__ int   g_count[E];
__device__ int   g_plist[E][T];
__device__ float g_wlist[E][T];

__device__ __align__(16) __half g_xf[T*D];
__device__ __align__(16) __half g_hf[(size_t)NPAIR*H];
__device__ float g_yp[(size_t)NPAIR*D];

// ---------------- helpers ----------------
__device__ __forceinline__ uint32_t smem_u32(const void* p) {
    uint32_t a;
    asm("{ .reg .u64 t; cvta.to.shared.u64 t, %1; cvt.u32.u64 %0, t; }" : "=r"(a) : "l"(p));
    return a;
}
__device__ __forceinline__ void cp16(uint32_t dst, const void* src) {
    asm volatile("cp.async.cg.shared.global [%0], [%1], 16;" :: "r"(dst), "l"(src));
}
#define CP_COMMIT() asm volatile("cp.async.commit_group;" ::: "memory")
#define CP_WAIT1()  asm volatile("cp.async.wait_group 1;" ::: "memory")

__device__ __forceinline__ void mma16816(float* c, const uint32_t* a, const uint32_t* b) {
    asm volatile("mma.sync.aligned.m16n8k16.row.col.f32.f16.f16.f32 "
        "{%0,%1,%2,%3}, {%4,%5,%6,%7}, {%8,%9}, {%0,%1,%2,%3};"
        : "+f"(c[0]), "+f"(c[1]), "+f"(c[2]), "+f"(c[3])
        : "r"(a[0]), "r"(a[1]), "r"(a[2]), "r"(a[3]), "r"(b[0]), "r"(b[1]));
}
__device__ __forceinline__ void ldA(uint32_t* a, const char* tile, int rm, int kk, int g, int q) {
    const char* p = tile + (rm + g) * STRIDE + (kk + q * 2) * 2;
    a[0] = *(const uint32_t*)p;
    a[1] = *(const uint32_t*)(p + 8 * STRIDE);
    a[2] = *(const uint32_t*)(p + 16);
    a[3] = *(const uint32_t*)(p + 8 * STRIDE + 16);
}
__device__ __forceinline__ void ldB(uint32_t* b, const char* tile, int cn, int kk, int g, int q) {
    const char* p = tile + (cn + g) * STRIDE + (kk + q * 2) * 2;
    b[0] = *(const uint32_t*)p;
    b[1] = *(const uint32_t*)(p + 16);
}
__device__ __forceinline__ uint32_t h2u(__half2 v) { return *reinterpret_cast<uint32_t*>(&v); }

// pack 8 fp32 (two float4) -> uint4 of 8 fp16
__device__ __forceinline__ uint4 pack8(const float4 A, const float4 B) {
    return make_uint4(
        h2u(__floats2half2_rn(A.x, A.y)), h2u(__floats2half2_rn(A.z, A.w)),
        h2u(__floats2half2_rn(B.x, B.y)), h2u(__floats2half2_rn(B.z, B.w)));
}

// ---------------- convert fp32 -> fp16 (x only), 4-way strip-mined ----------------
__global__ __launch_bounds__(256) void cvt4_kernel(const float4* __restrict__ src,
                                                   uint4* __restrict__ dst, int q) {
    int i = blockIdx.x * 256 + threadIdx.x;
    if (i >= q) return;
    float4 a0 = src[2*(size_t)i],           b0 = src[2*(size_t)i + 1];
    float4 a1 = src[2*((size_t)i + q)],     b1 = src[2*((size_t)i + q) + 1];
    float4 a2 = src[2*((size_t)i + 2*q)],   b2 = src[2*((size_t)i + 2*q) + 1];
    float4 a3 = src[2*((size_t)i + 3*q)],   b3 = src[2*((size_t)i + 3*q) + 1];
    dst[i]       = pack8(a0, b0);
    dst[i + q]   = pack8(a1, b1);
    dst[i + 2*q] = pack8(a2, b2);
    dst[i + 3*q] = pack8(a3, b3);
}

// ---------------- gate / routing ----------------
__global__ void gate_kernel(const float* __restrict__ x, const float* __restrict__ Wg) {
    int t = blockIdx.x;
    int warp = threadIdx.x >> 5, lane = threadIdx.x & 31;
    __shared__ float logits[E];
    const float* xr = x + (size_t)t * D;
    const float* wr = Wg + (size_t)warp * D;
    float s = 0.f;
    #pragma unroll
    for (int j = 0; j < D / 128; j++) {
        int i = lane * 4 + j * 128;
        float4 xv = *(const float4*)(xr + i);
        float4 wv = *(const float4*)(wr + i);
        s += xv.x * wv.x + xv.y * wv.y + xv.z * wv.z + xv.w * wv.w;
    }
    #pragma unroll
    for (int o = 16; o; o >>= 1) s += __shfl_xor_sync(0xffffffffu, s, o);
    if (lane == 0) logits[warp] = s;
    __syncthreads();
    if (threadIdx.x == 0) {
        float m = logits[0];
        #pragma unroll
        for (int e2 = 1; e2 < E; e2++) m = fmaxf(m, logits[e2]);
        float p[E];
        #pragma unroll
        for (int e2 = 0; e2 < E; e2++) p[e2] = expf(logits[e2] - m);
        int i0 = 0;
        #pragma unroll
        for (int e2 = 1; e2 < E; e2++) if (p[e2] > p[i0]) i0 = e2;
        int i1 = (i0 == 0) ? 1 : 0;
        #pragma unroll
        for (int e2 = 0; e2 < E; e2++) if (e2 != i0 && p[e2] > p[i1]) i1 = e2;
        float inv = 1.f / (p[i0] + p[i1]);
        g_pidx[2*t]   = i0; g_pw[2*t]   = p[i0] * inv;
        g_pidx[2*t+1] = i1; g_pw[2*t+1] = p[i1] * inv;
    }
}

__global__ void build_lists_kernel() {
    int e = blockIdx.x, tid = threadIdx.x;
    int lane = tid & 31, warp = tid >> 5;
    __shared__ int warp_cnt[8];
    __shared__ int base_s;
    if (tid == 0) base_s = 0;
    __syncthreads();
    for (int c = 0; c < NPAIR; c += 256) {
        int i = c + tid;
        bool m = (g_pidx[i] == e);
        unsigned bal = __ballot_sync(0xffffffffu, m);
        if (lane == 0) warp_cnt[warp] = __popc(bal);
        __syncthreads();
        int pos = base_s;
        for (int w = 0; w < warp; w++) pos += warp_cnt[w];
        pos += __popc(bal & ((1u << lane) - 1u));
        if (m) { g_plist[e][pos] = i; g_wlist[e][pos] = g_pw[i]; }
        __syncthreads();
        if (tid == 0) {
            int tot = 0;
            #pragma unroll
            for (int w = 0; w < 8; w++) tot += warp_cnt[w];
            base_s += tot;
        }
        __syncthreads();
    }
    if (tid == 0) g_count[e] = base_s;
}

// ---------------- UP GEMM: h = silu(x W1^T) * (x W3^T), fp16, in-loader W cvt ----------------
// Stage (20480 B): A 0 (128x80), B1 10240 (64x80), B3 15360 (64x80)
#define UP_STG 20480
#define UP_SMEM (1024 + 2*UP_STG)

__global__ __launch_bounds__(256, 2) void ffn_up_mma(const float* __restrict__ W1,
                                                     const float* __restrict__ W3) {
    int e = blockIdx.z;
    int cnt = g_count[e];
    int m0 = blockIdx.x * BM;
    if (m0 >= cnt) return;
    int n0 = blockIdx.y * BN;

    extern __shared__ __align__(128) char smem[];
    int* ps = (int*)smem;
    int tid = threadIdx.x;
    if (tid < BM) { int s = m0 + tid; ps[tid] = (s < cnt) ? g_plist[e][s] : -1; }
    __syncthreads();

    char* tiles = smem + 1024;
    uint32_t tiles_u = smem_u32(tiles);
    const float* W1e = W1 + (size_t)e * H * D + (size_t)n0 * D;
    const float* W3e = W3 + (size_t)e * H * D + (size_t)n0 * D;
    const int NS = D / BK;  // 32

    // A loader: 512 chunks (128 rows x 4), 2 per thread, fp16 via cp.async
    auto issueA = [&](int s) {
        uint32_t tb = tiles_u + (s & 1) * UP_STG;
        int k0 = s * BK;
        #pragma unroll
        for (int j = 0; j < 2; j++) {
            int idx = tid + j * 256;
            int r = idx >> 2, c = idx & 3;
            int pr = ps[r];
            int tok = (pr < 0) ? 0 : (pr >> 1);
            cp16(tb + r * STRIDE + c * 16, g_xf + (size_t)tok * D + k0 + c * 8);
        }
    };
    // B loader: 256 chunks per matrix, 1 per thread; fp32 LDG -> regs
    int br = tid >> 2, bc = tid & 3;
    auto ldgB = [&](int s, float4* r1, float4* r3) {
        int k0 = s * BK;
        const float* p1 = W1e + (size_t)br * D + k0 + bc * 8;
        const float* p3 = W3e + (size_t)br * D + k0 + bc * 8;
        r1[0] = ((const float4*)p1)[0]; r1[1] = ((const float4*)p1)[1];
        r3[0] = ((const float4*)p3)[0]; r3[1] = ((const float4*)p3)[1];
    };
    auto stsB = [&](int s, const float4* r1, const float4* r3) {
        char* tb = tiles + (s & 1) * UP_STG;
        *(uint4*)(tb + 10240 + br * STRIDE + bc * 16) = pack8(r1[0], r1[1]);
        *(uint4*)(tb + 15360 + br * STRIDE + bc * 16) = pack8(r3[0], r3[1]);
    };

    int wid = tid >> 5, lane = tid & 31;
    int wm = wid & 3, wn = wid >> 2;
    int g = lane >> 2, q = lane & 3;

    float a1[2][4][4], a3[2][4][4];
    #pragma unroll
    for (int i = 0; i < 2; i++)
        #pragma unroll
        for (int j = 0; j < 4; j++)
            #pragma unroll
            for (int k = 0; k < 4; k++) { a1[i][j][k] = 0.f; a3[i][j][k] = 0.f; }

    issueA(0); CP_COMMIT();
    issueA(1); CP_COMMIT();
    float4 rB1[2], rB3[2];
    ldgB(0, rB1, rB3);

    for (int s = 0; s < NS; s++) {
        stsB(s, rB1, rB3);
        if (s + 1 < NS) ldgB(s + 1, rB1, rB3);
        CP_WAIT1();
        __syncthreads();
        const char* tb = tiles + (s & 1) * UP_STG;
        const char* At  = tb;
        const char* B1t = tb + 10240;
        const char* B3t = tb + 15360;
        #pragma unroll
        for (int kk = 0; kk < BK; kk += 16) {
            uint32_t fA[2][4];
            #pragma unroll
            for (int mi = 0; mi < 2; mi++)
                ldA(fA[mi], At, wm * 32 + mi * 16, kk, g, q);
            uint32_t b1[4][2], b3[4][2];
            #pragma unroll
            for (int nj = 0; nj < 4; nj++) {
                ldB(b1[nj], B1t, wn * 32 + nj * 8, kk, g, q);
                ldB(b3[nj], B3t, wn * 32 + nj * 8, kk, g, q);
            }
            #pragma unroll
            for (int mi = 0; mi < 2; mi++)
                #pragma unroll
                for (int nj = 0; nj < 4; nj++) {
                    mma16816(a1[mi][nj], fA[mi], b1[nj]);
                    mma16816(a3[mi][nj], fA[mi], b3[nj]);
                }
        }
        __syncthreads();
        if (s + 2 < NS) issueA(s + 2);
        CP_COMMIT();
    }

    // epilogue: silu(z)*u, store fp16
    #pragma unroll
    for (int mi = 0; mi < 2; mi++) {
        #pragma unroll
        for (int nj = 0; nj < 4; nj++) {
            int lr0 = wm * 32 + mi * 16 + g, lr1 = lr0 + 8;
            int n = n0 + wn * 32 + nj * 8 + q * 2;
            float* c1 = a1[mi][nj];
            float* c3 = a3[mi][nj];
            #pragma unroll
            for (int half = 0; half < 2; half++) {
                int p = ps[half ? lr1 : lr0];
                if (p < 0) continue;
                float z0 = c1[half * 2], z1 = c1[half * 2 + 1];
                float u0 = c3[half * 2], u1 = c3[half * 2 + 1];
                float h0 = (z0 / (1.f + __expf(-z0))) * u0;
                float h1 = (z1 / (1.f + __expf(-z1))) * u1;
                *(uint32_t*)(g_hf + (size_t)p * H + n) = h2u(__floats2half2_rn(h0, h1));
            }
        }
    }
}

// ---------------- DOWN GEMM: yp = w * (h W2^T), fp16, in-loader W cvt ----------------
// Stage (15360 B): A 0 (128x80), B 10240 (64x80)
#define DN_STG 15360
#define DN_SMEM (1024 + 2*DN_STG)

__global__ __launch_bounds__(256, 2) void ffn_down_mma(const float* __restrict__ W2) {
    int e = blockIdx.z;
    int cnt = g_count[e];
    int m0 = blockIdx.x * BM;
    if (m0 >= cnt) return;
    int n0 = blockIdx.y * BN;

    extern __shared__ __align__(128) char smem[];
    int* ps = (int*)smem;
    float* pwS = (float*)(smem + 512);
    int tid = threadIdx.x;
    if (tid < BM) {
        int s = m0 + tid;
        if (s < cnt) { ps[tid] = g_plist[e][s]; pwS[tid] = g_wlist[e][s]; }
        else         { ps[tid] = -1;            pwS[tid] = 0.f; }
    }
    __syncthreads();

    char* tiles = smem + 1024;
    uint32_t tiles_u = smem_u32(tiles);
    const float* W2e = W2 + (size_t)e * D * H + (size_t)n0 * H;
    const int NS = H / BK;  // 88

    auto issueA = [&](int s) {
        uint32_t tb = tiles_u + (s & 1) * DN_STG;
        int k0 = s * BK;
        #pragma unroll
        for (int j = 0; j < 2; j++) {
            int idx = tid + j * 256;
            int r = idx >> 2, c = idx & 3;
            int p = ps[r];
            int pr = (p < 0) ? 0 : p;
            cp16(tb + r * STRIDE + c * 16, g_hf + (size_t)pr * H + k0 + c * 8);
        }
    };
    int br = tid >> 2, bc = tid & 3;
    auto ldgB = [&](int s, float4* r2) {
        int k0 = s * BK;
        const float* p2 = W2e + (size_t)br * H + k0 + bc * 8;
        r2[0] = ((const float4*)p2)[0]; r2[1] = ((const float4*)p2)[1];
    };
    auto stsB = [&](int s, const float4* r2) {
        char* tb = tiles + (s & 1) * DN_STG;
        *(uint4*)(tb + 10240 + br * STRIDE + bc * 16) = pack8(r2[0], r2[1]);
    };

    int wid = tid >> 5, lane = tid & 31;
    int wm = wid & 3, wn = wid >> 2;
    int g = lane >> 2, q = lane & 3;

    float acc[2][4][4];
    #pragma unroll
    for (int i = 0; i < 2; i++)
        #pragma unroll
        for (int j = 0; j < 4; j++)
            #pragma unroll
            for (int k = 0; k < 4; k++) acc[i][j][k] = 0.f;

    issueA(0); CP_COMMIT();
    issueA(1); CP_COMMIT();
    float4 rB[2];
    ldgB(0, rB);

    for (int s = 0; s < NS; s++) {
        stsB(s, rB);
        if (s + 1 < NS) ldgB(s + 1, rB);
        CP_WAIT1();
        __syncthreads();
        const char* tb = tiles + (s & 1) * DN_STG;
        const char* At = tb;
        const char* Bt = tb + 10240;
        #pragma unroll
        for (int kk = 0; kk < BK; kk += 16) {
            uint32_t fA[2][4];
            #pragma unroll
            for (int mi = 0; mi < 2; mi++)
                ldA(fA[mi], At, wm * 32 + mi * 16, kk, g, q);
            uint32_t b[4][2];
            #pragma unroll
            for (int nj = 0; nj < 4; nj++)
                ldB(b[nj], Bt, wn * 32 + nj * 8, kk, g, q);
            #pragma unroll
            for (int mi = 0; mi < 2; mi++)
                #pragma unroll
                for (int nj = 0; nj < 4; nj++)
                    mma16816(acc[mi][nj], fA[mi], b[nj]);
        }
        __syncthreads();
        if (s + 2 < NS) issueA(s + 2);
        CP_COMMIT();
    }

    #pragma unroll
    for (int mi = 0; mi < 2; mi++) {
        #pragma unroll
        for (int nj = 0; nj < 4; nj++) {
            int lr0 = wm * 32 + mi * 16 + g, lr1 = lr0 + 8;
            int n = n0 + wn * 32 + nj * 8 + q * 2;
            float* c = acc[mi][nj];
            #pragma unroll
            for (int half = 0; half < 2; half++) {
                int lr = half ? lr1 : lr0;
                int p = ps[lr];
                if (p < 0) continue;
                float w = pwS[lr];
                float2 v = make_float2(w * c[half * 2], w * c[half * 2 + 1]);
                *(float2*)(g_yp + (size_t)p * D + n) = v;
            }
        }
    }
}

// ---------------- combine ----------------
__global__ void combine_kernel(float* __restrict__ y) {
    int i = blockIdx.x * 256 + threadIdx.x;
    int t = i / D, d = i - t * D;
    y[i] = g_yp[(size_t)(2 * t) * D + d] + g_yp[(size_t)(2 * t + 1) * D + d];
}

// ---------------- launch ----------------
extern "C" void kernel_launch(void* const* d_in, const int* in_sizes, int n_in,
                              void* d_out, int out_size) {
    const float* x  = (const float*)d_in[0];
    const float* Wg = (const float*)d_in[1];
    const float* W1 = (const float*)d_in[2];
    const float* W2 = (const float*)d_in[3];
    const float* W3 = (const float*)d_in[4];
    float* y = (float*)d_out;

    cudaFuncSetAttribute(ffn_up_mma,   cudaFuncAttributeMaxDynamicSharedMemorySize, UP_SMEM);
    cudaFuncSetAttribute(ffn_down_mma, cudaFuncAttributeMaxDynamicSharedMemorySize, DN_SMEM);

    // convert x fp32 -> fp16 (tiny; weights converted in-loader)
    {
        int qX = T * D / 8 / 4;
        __half* xf;
        cudaGetSymbolAddress((void**)&xf, g_xf);
        cvt4_kernel<<<(qX + 255) / 256, 256>>>((const float4*)x, (uint4*)xf, qX);
    }

    gate_kernel<<<T, 256>>>(x, Wg);
    build_lists_kernel<<<E, 256>>>();

    dim3 g1(T / BM, H / BN, E);   // 16 x 44 x 8
    ffn_up_mma<<<g1, 256, UP_SMEM>>>(W1, W3);

    dim3 g2(T / BM, D / BN, E);   // 16 x 16 x 8
    ffn_down_mma<<<g2, 256, DN_SMEM>>>(W2);

    combine_kernel<<<(T * D) / 256, 256>>>(y);
}

// round 16
// speedup vs baseline: 1.1886x; 1.1886x over previous
#include <cuda_runtime.h>
#include <cuda_fp16.h>
#include <cstdint>
#include <math.h>

#define T 2048      // tokens
#define D 1024      // model dim
#define H 2816      // ffn hidden
#define E 8         // experts
#define NPAIR (T*2) // token-expert pairs

#define BM 128
#define BN 64
#define BK 32
#define STRIDE 80   // padded bytes per k-row (multiple of 16; conflict-free)

// ---------------- device globals (no allocation allowed) ----------------
__device__ int   g_pidx[NPAIR];
__device__ float g_pw[NPAIR];
__device__ int   g_count[E];
__device__ int   g_plist[E][T];
__device__ float g_wlist[E][T];

__device__ __align__(16) __half g_xf[T*D];
__device__ __align__(16) __half g_W1f[(size_t)E*H*D];
__device__ __align__(16) __half g_W3f[(size_t)E*H*D];
__device__ __align__(16) __half g_W2f[(size_t)E*D*H];
__device__ __align__(16) __half g_hf[(size_t)NPAIR*H];
__device__ float g_yp[(size_t)NPAIR*D];

// ---------------- helpers ----------------
__device__ __forceinline__ uint32_t smem_u32(const void* p) {
    uint32_t a;
    asm("{ .reg .u64 t; cvta.to.shared.u64 t, %1; cvt.u32.u64 %0, t; }" : "=r"(a) : "l"(p));
    return a;
}
__device__ __forceinline__ void cp16(uint32_t dst, const void* src) {
    asm volatile("cp.async.cg.shared.global [%0], [%1], 16;" :: "r"(dst), "l"(src));
}
#define CP_COMMIT() asm volatile("cp.async.commit_group;" ::: "memory")
#define CP_WAIT1()  asm volatile("cp.async.wait_group 1;" ::: "memory")

__device__ __forceinline__ void mma16816(float* c, const uint32_t* a, const uint32_t* b) {
    asm volatile("mma.sync.aligned.m16n8k16.row.col.f32.f16.f16.f32 "
        "{%0,%1,%2,%3}, {%4,%5,%6,%7}, {%8,%9}, {%0,%1,%2,%3};"
        : "+f"(c[0]), "+f"(c[1]), "+f"(c[2]), "+f"(c[3])
        : "r"(a[0]), "r"(a[1]), "r"(a[2]), "r"(a[3]), "r"(b[0]), "r"(b[1]));
}
__device__ __forceinline__ void ldA(uint32_t* a, const char* tile, int rm, int kk, int g, int q) {
    const char* p = tile + (rm + g) * STRIDE + (kk + q * 2) * 2;
    a[0] = *(const uint32_t*)p;
    a[1] = *(const uint32_t*)(p + 8 * STRIDE);
    a[2] = *(const uint32_t*)(p + 16);
    a[3] = *(const uint32_t*)(p + 8 * STRIDE + 16);
}
__device__ __forceinline__ void ldB(uint32_t* b, const char* tile, int cn, int kk, int g, int q) {
    const char* p = tile + (cn + g) * STRIDE + (kk + q * 2) * 2;
    b[0] = *(const uint32_t*)p;
    b[1] = *(const uint32_t*)(p + 16);
}
__device__ __forceinline__ uint32_t h2u(__half2 v) { return *reinterpret_cast<uint32_t*>(&v); }

// pack 8 fp32 (two float4) -> uint4 of 8 fp16
__device__ __forceinline__ uint4 pack8(const float4 A, const float4 B) {
    return make_uint4(
        h2u(__floats2half2_rn(A.x, A.y)), h2u(__floats2half2_rn(A.z, A.w)),
        h2u(__floats2half2_rn(B.x, B.y)), h2u(__floats2half2_rn(B.z, B.w)));
}

// ---------------- convert fp32 -> fp16, 4-way strip-mined (MLP=8) ----------------
__global__ __launch_bounds__(256) void cvt4_kernel(const float4* __restrict__ src,
                                                   uint4* __restrict__ dst, int q) {
    int i = blockIdx.x * 256 + threadIdx.x;
    if (i >= q) return;
    float4 a0 = src[2*(size_t)i],           b0 = src[2*(size_t)i + 1];
    float4 a1 = src[2*((size_t)i + q)],     b1 = src[2*((size_t)i + q) + 1];
    float4 a2 = src[2*((size_t)i + 2*q)],   b2 = src[2*((size_t)i + 2*q) + 1];
    float4 a3 = src[2*((size_t)i + 3*q)],   b3 = src[2*((size_t)i + 3*q) + 1];
    dst[i]       = pack8(a0, b0);
    dst[i + q]   = pack8(a1, b1);
    dst[i + 2*q] = pack8(a2, b2);
    dst[i + 3*q] = pack8(a3, b3);
}

// ---------------- gate / routing ----------------
__global__ void gate_kernel(const float* __restrict__ x, const float* __restrict__ Wg) {
    int t = blockIdx.x;
    int warp = threadIdx.x >> 5, lane = threadIdx.x & 31;
    __shared__ float logits[E];
    const float* xr = x + (size_t)t * D;
    const float* wr = Wg + (size_t)warp * D;
    float s = 0.f;
    #pragma unroll
    for (int j = 0; j < D / 128; j++) {
        int i = lane * 4 + j * 128;
        float4 xv = *(const float4*)(xr + i);
        float4 wv = *(const float4*)(wr + i);
        s += xv.x * wv.x + xv.y * wv.y + xv.z * wv.z + xv.w * wv.w;
    }
    #pragma unroll
    for (int o = 16; o; o >>= 1) s += __shfl_xor_sync(0xffffffffu, s, o);
    if (lane == 0) logits[warp] = s;
    __syncthreads();
    if (threadIdx.x == 0) {
        float m = logits[0];
        #pragma unroll
        for (int e2 = 1; e2 < E; e2++) m = fmaxf(m, logits[e2]);
        float p[E];
        #pragma unroll
        for (int e2 = 0; e2 < E; e2++) p[e2] = expf(logits[e2] - m);
        int i0 = 0;
        #pragma unroll
        for (int e2 = 1; e2 < E; e2++) if (p[e2] > p[i0]) i0 = e2;
        int i1 = (i0 == 0) ? 1 : 0;
        #pragma unroll
        for (int e2 = 0; e2 < E; e2++) if (e2 != i0 && p[e2] > p[i1]) i1 = e2;
        float inv = 1.f / (p[i0] + p[i1]);
        g_pidx[2*t]   = i0; g_pw[2*t]   = p[i0] * inv;
        g_pidx[2*t+1] = i1; g_pw[2*t+1] = p[i1] * inv;
    }
}

__global__ void build_lists_kernel() {
    int e = blockIdx.x, tid = threadIdx.x;
    int lane = tid & 31, warp = tid >> 5;
    __shared__ int warp_cnt[8];
    __shared__ int base_s;
    if (tid == 0) base_s = 0;
    __syncthreads();
    for (int c = 0; c < NPAIR; c += 256) {
        int i = c + tid;
        bool m = (g_pidx[i] == e);
        unsigned bal = __ballot_sync(0xffffffffu, m);
        if (lane == 0) warp_cnt[warp] = __popc(bal);
        __syncthreads();
        int pos = base_s;
        for (int w = 0; w < warp; w++) pos += warp_cnt[w];
        pos += __popc(bal & ((1u << lane) - 1u));
        if (m) { g_plist[e][pos] = i; g_wlist[e][pos] = g_pw[i]; }
        __syncthreads();
        if (tid == 0) {
            int tot = 0;
            #pragma unroll
            for (int w = 0; w < 8; w++) tot += warp_cnt[w];
            base_s += tot;
        }
        __syncthreads();
    }
    if (tid == 0) g_count[e] = base_s;
}

// ---------------- UP GEMM: h = silu(x W1^T) * (x W3^T), fp16 single-pass ----------------
// Stage (20480 B): A 0 (128x80), B1 10240 (64x80), B3 15360 (64x80)
#define UP_STG 20480
#define UP_SMEM (1024 + 2*UP_STG)

__global__ __launch_bounds__(256, 2) void ffn_up_mma() {
    int e = blockIdx.z;
    int cnt = g_count[e];
    int m0 = blockIdx.x * BM;
    if (m0 >= cnt) return;
    int n0 = blockIdx.y * BN;

    extern __shared__ __align__(128) char smem[];
    int* ps = (int*)smem;
    int tid = threadIdx.x;
    if (tid < BM) { int s = m0 + tid; ps[tid] = (s < cnt) ? g_plist[e][s] : -1; }
    __syncthreads();

    char* tiles = smem + 1024;
    uint32_t tiles_u = smem_u32(tiles);
    const size_t wbase = (size_t)e * H * D + (size_t)n0 * D;
    const int NS = D / BK;  // 32

    auto issue = [&](int s) {
        uint32_t tb = tiles_u + (s & 1) * UP_STG;
        int k0 = s * BK;
        #pragma unroll
        for (int j = 0; j < 4; j++) {
            int idx = tid + j * 256;
            if (idx < 512) {          // A: x rows gathered by pair
                int r = idx >> 2, c = idx & 3;
                int pr = ps[r];
                int tok = (pr < 0) ? 0 : (pr >> 1);
                cp16(tb + r * STRIDE + c * 16, g_xf + (size_t)tok * D + k0 + c * 8);
            } else if (idx < 768) {   // B1
                int i2 = idx - 512, r = i2 >> 2, c = i2 & 3;
                cp16(tb + 10240 + r * STRIDE + c * 16, g_W1f + wbase + (size_t)r * D + k0 + c * 8);
            } else {                  // B3
                int i2 = idx - 768, r = i2 >> 2, c = i2 & 3;
                cp16(tb + 15360 + r * STRIDE + c * 16, g_W3f + wbase + (size_t)r * D + k0 + c * 8);
            }
        }
    };

    int wid = tid >> 5, lane = tid & 31;
    int wm = wid & 3, wn = wid >> 2;
    int g = lane >> 2, q = lane & 3;

    float a1[2][4][4], a3[2][4][4];
    #pragma unroll
    for (int i = 0; i < 2; i++)
        #pragma unroll
        for (int j = 0; j < 4; j++)
            #pragma unroll
            for (int k = 0; k < 4; k++) { a1[i][j][k] = 0.f; a3[i][j][k] = 0.f; }

    issue(0); CP_COMMIT();
    issue(1); CP_COMMIT();

    for (int s = 0; s < NS; s++) {
        CP_WAIT1();
        __syncthreads();
        const char* tb = tiles + (s & 1) * UP_STG;
        const char* At  = tb;
        const char* B1t = tb + 10240;
        const char* B3t = tb + 15360;
        #pragma unroll
        for (int kk = 0; kk < BK; kk += 16) {
            uint32_t fA[2][4];
            #pragma unroll
            for (int mi = 0; mi < 2; mi++)
                ldA(fA[mi], At, wm * 32 + mi * 16, kk, g, q);
            uint32_t b1[4][2], b3[4][2];
            #pragma unroll
            for (int nj = 0; nj < 4; nj++) {
                ldB(b1[nj], B1t, wn * 32 + nj * 8, kk, g, q);
                ldB(b3[nj], B3t, wn * 32 + nj * 8, kk, g, q);
            }
            #pragma unroll
            for (int mi = 0; mi < 2; mi++)
                #pragma unroll
                for (int nj = 0; nj < 4; nj++) {
                    mma16816(a1[mi][nj], fA[mi], b1[nj]);
                    mma16816(a3[mi][nj], fA[mi], b3[nj]);
                }
        }
        __syncthreads();
        if (s + 2 < NS) issue(s + 2);
        CP_COMMIT();
    }

    // epilogue: silu(z)*u, store fp16
    #pragma unroll
    for (int mi = 0; mi < 2; mi++) {
        #pragma unroll
        for (int nj = 0; nj < 4; nj++) {
            int lr0 = wm * 32 + mi * 16 + g, lr1 = lr0 + 8;
            int n = n0 + wn * 32 + nj * 8 + q * 2;
            float* c1 = a1[mi][nj];
            float* c3 = a3[mi][nj];
            #pragma unroll
            for (int half = 0; half < 2; half++) {
                int p = ps[half ? lr1 : lr0];
                if (p < 0) continue;
                float z0 = c1[half * 2], z1 = c1[half * 2 + 1];
                float u0 = c3[half * 2], u1 = c3[half * 2 + 1];
                float h0 = (z0 / (1.f + __expf(-z0))) * u0;
                float h1 = (z1 / (1.f + __expf(-z1))) * u1;
                *(uint32_t*)(g_hf + (size_t)p * H + n) = h2u(__floats2half2_rn(h0, h1));
            }
        }
    }
}

// ---------------- DOWN GEMM: yp = w * (h W2^T), fp16 single-pass ----------------
// Stage (15360 B): A 0 (128x80), B 10240 (64x80)
#define DN_STG 15360
#define DN_SMEM (1024 + 2*DN_STG)

__global__ __launch_bounds__(256, 2) void ffn_down_mma() {
    int e = blockIdx.z;
    int cnt = g_count[e];
    int m0 = blockIdx.x * BM;
    if (m0 >= cnt) return;
    int n0 = blockIdx.y * BN;

    extern __shared__ __align__(128) char smem[];
    int* ps = (int*)smem;
    float* pwS = (float*)(smem + 512);
    int tid = threadIdx.x;
    if (tid < BM) {
        int s = m0 + tid;
        if (s < cnt) { ps[tid] = g_plist[e][s]; pwS[tid] = g_wlist[e][s]; }
        else         { ps[tid] = -1;            pwS[tid] = 0.f; }
    }
    __syncthreads();

    char* tiles = smem + 1024;
    uint32_t tiles_u = smem_u32(tiles);
    const size_t wbase = (size_t)e * D * H + (size_t)n0 * H;
    const int NS = H / BK;  // 88

    auto issue = [&](int s) {
        uint32_t tb = tiles_u + (s & 1) * DN_STG;
        int k0 = s * BK;
        #pragma unroll
        for (int j = 0; j < 3; j++) {
            int idx = tid + j * 256;
            if (idx < 512) {          // A: h rows by pair
                int r = idx >> 2, c = idx & 3;
                int p = ps[r];
                int pr = (p < 0) ? 0 : p;
                cp16(tb + r * STRIDE + c * 16, g_hf + (size_t)pr * H + k0 + c * 8);
            } else {                  // B: W2 rows
                int i2 = idx - 512, r = i2 >> 2, c = i2 & 3;
                cp16(tb + 10240 + r * STRIDE + c * 16, g_W2f + wbase + (size_t)r * H + k0 + c * 8);
            }
        }
    };

    int wid = tid >> 5, lane = tid & 31;
    int wm = wid & 3, wn = wid >> 2;
    int g = lane >> 2, q = lane & 3;

    float acc[2][4][4];
    #pragma unroll
    for (int i = 0; i < 2; i++)
        #pragma unroll
        for (int j = 0; j < 4; j++)
            #pragma unroll
            for (int k = 0; k < 4; k++) acc[i][j][k] = 0.f;

    issue(0); CP_COMMIT();
    issue(1); CP_COMMIT();

    for (int s = 0; s < NS; s++) {
        CP_WAIT1();
        __syncthreads();
        const char* tb = tiles + (s & 1) * DN_STG;
        const char* At = tb;
        const char* Bt = tb + 10240;
        #pragma unroll
        for (int kk = 0; kk < BK; kk += 16) {
            uint32_t fA[2][4];
            #pragma unroll
            for (int mi = 0; mi < 2; mi++)
                ldA(fA[mi], At, wm * 32 + mi * 16, kk, g, q);
            uint32_t b[4][2];
            #pragma unroll
            for (int nj = 0; nj < 4; nj++)
                ldB(b[nj], Bt, wn * 32 + nj * 8, kk, g, q);
            #pragma unroll
            for (int mi = 0; mi < 2; mi++)
                #pragma unroll
                for (int nj = 0; nj < 4; nj++)
                    mma16816(acc[mi][nj], fA[mi], b[nj]);
        }
        __syncthreads();
        if (s + 2 < NS) issue(s + 2);
        CP_COMMIT();
    }

    #pragma unroll
    for (int mi = 0; mi < 2; mi++) {
        #pragma unroll
        for (int nj = 0; nj < 4; nj++) {
            int lr0 = wm * 32 + mi * 16 + g, lr1 = lr0 + 8;
            int n = n0 + wn * 32 + nj * 8 + q * 2;
            float* c = acc[mi][nj];
            #pragma unroll
            for (int half = 0; half < 2; half++) {
                int lr = half ? lr1 : lr0;
                int p = ps[lr];
                if (p < 0) continue;
                float w = pwS[lr];
                float2 v = make_float2(w * c[half * 2], w * c[half * 2 + 1]);
                *(float2*)(g_yp + (size_t)p * D + n) = v;
            }
        }
    }
}

// ---------------- combine ----------------
__global__ void combine_kernel(float* __restrict__ y) {
    int i = blockIdx.x * 256 + threadIdx.x;
    int t = i / D, d = i - t * D;
    y[i] = g_yp[(size_t)(2 * t) * D + d] + g_yp[(size_t)(2 * t + 1) * D + d];
}

// ---------------- launch ----------------
extern "C" void kernel_launch(void* const* d_in, const int* in_sizes, int n_in,
                              void* d_out, int out_size) {
    const float* x  = (const float*)d_in[0];
    const float* Wg = (const float*)d_in[1];
    const float* W1 = (const float*)d_in[2];
    const float* W2 = (const float*)d_in[3];
    const float* W3 = (const float*)d_in[4];
    float* y = (float*)d_out;

    // One-time infra (handles only; no device memory). Work per call is identical.
    static cudaStream_t s_w2 = nullptr, s_route = nullptr;
    static cudaEvent_t  e_fork = nullptr, e_w2 = nullptr, e_route = nullptr;
    if (!s_w2) {
        cudaStreamCreateWithFlags(&s_w2,    cudaStreamNonBlocking);
        cudaStreamCreateWithFlags(&s_route, cudaStreamNonBlocking);
        cudaEventCreateWithFlags(&e_fork,  cudaEventDisableTiming);
        cudaEventCreateWithFlags(&e_w2,    cudaEventDisableTiming);
        cudaEventCreateWithFlags(&e_route, cudaEventDisableTiming);
        cudaFuncSetAttribute(ffn_up_mma,   cudaFuncAttributeMaxDynamicSharedMemorySize, UP_SMEM);
        cudaFuncSetAttribute(ffn_down_mma, cudaFuncAttributeMaxDynamicSharedMemorySize, DN_SMEM);
    }

    int qW = (int)((size_t)E * H * D / 8 / 4);
    int qX = T * D / 8 / 4;
    __half *w1f, *w3f, *w2f, *xf;
    cudaGetSymbolAddress((void**)&w1f, g_W1f);
    cudaGetSymbolAddress((void**)&w3f, g_W3f);
    cudaGetSymbolAddress((void**)&w2f, g_W2f);
    cudaGetSymbolAddress((void**)&xf,  g_xf);

    // fork
    cudaEventRecord(e_fork, 0);
    cudaStreamWaitEvent(s_w2,    e_fork, 0);
    cudaStreamWaitEvent(s_route, e_fork, 0);

    // aux1: W2 convert (needed only by down GEMM)
    cvt4_kernel<<<(qW + 255) / 256, 256, 0, s_w2>>>((const float4*)W2, (uint4*)w2f, qW);
    cudaEventRecord(e_w2, s_w2);

    // aux2: routing (reads fp32 x directly)
    gate_kernel<<<T, 256, 0, s_route>>>(x, Wg);
    build_lists_kernel<<<E, 256, 0, s_route>>>();
    cudaEventRecord(e_route, s_route);

    // main: converts needed by the up GEMM
    cvt4_kernel<<<(qW + 255) / 256, 256>>>((const float4*)W1, (uint4*)w1f, qW);
    cvt4_kernel<<<(qW + 255) / 256, 256>>>((const float4*)W3, (uint4*)w3f, qW);
    cvt4_kernel<<<(qX + 255) / 256, 256>>>((const float4*)x,  (uint4*)xf,  qX);

    // join routing, run up GEMM (W2 convert overlaps with it on aux1)
    cudaStreamWaitEvent(0, e_route, 0);
    dim3 g1(T / BM, H / BN, E);   // 16 x 44 x 8
    ffn_up_mma<<<g1, 256, UP_SMEM>>>();

    // join W2 convert, run down GEMM
    cudaStreamWaitEvent(0, e_w2, 0);
    dim3 g2(T / BM, D / BN, E);   // 16 x 16 x 8
    ffn_down_mma<<<g2, 256, DN_SMEM>>>();

    combine_kernel<<<(T * D) / 256, 256>>>(y);
}